// round 6
// baseline (speedup 1.0000x reference)
#include <cuda_runtime.h>
#include <cuda_fp16.h>
#include <cstdint>

#define TT 64
#define BB 128
#define HH 200
#define RROWS 8192      // T*B
#define KTOT 1024       // packed K per channel (320 L + 384 M + 320 R)

// ---------------------------------------------------------------------------
// Scratch (__device__ globals; no cudaMalloc allowed)
// ---------------------------------------------------------------------------
__device__ float g_cur[(size_t)TT * 9 * BB * HH];    // [t][g][b][h]
__device__ __half g_Bh[(size_t)3 * HH * KTOT];       // hi fp16 split of W (K-packed)
__device__ __half g_Bm[(size_t)3 * HH * KTOT];       // lo fp16 split

// ---------------------------------------------------------------------------
// PTX helpers (plain sm_103-compatible: mma.sync / ldmatrix / cp.async)
// ---------------------------------------------------------------------------
__device__ __forceinline__ uint32_t smem_u32(const void* p) {
    uint32_t a;
    asm("{ .reg .u64 t; cvta.to.shared.u64 t, %1; cvt.u32.u64 %0, t; }" : "=r"(a) : "l"(p));
    return a;
}

#define CP16(dst, src) \
    asm volatile("cp.async.cg.shared.global [%0], [%1], 16;" :: "r"(dst), "l"(src) : "memory")
#define CP_COMMIT() asm volatile("cp.async.commit_group;" ::: "memory")
#define CP_WAIT1()  asm volatile("cp.async.wait_group 1;" ::: "memory")

#define LDSM_X4(r, addr) \
    asm volatile("ldmatrix.sync.aligned.m8n8.x4.shared.b16 {%0,%1,%2,%3}, [%4];" \
        : "=r"((r)[0]), "=r"((r)[1]), "=r"((r)[2]), "=r"((r)[3]) : "r"(addr))
#define LDSM_X2(r, addr) \
    asm volatile("ldmatrix.sync.aligned.m8n8.x2.shared.b16 {%0,%1}, [%2];" \
        : "=r"((r)[0]), "=r"((r)[1]) : "r"(addr))

#define MMA16816(d, a, b0, b1) \
    asm volatile("mma.sync.aligned.m16n8k16.row.col.f32.f16.f16.f32 " \
        "{%0,%1,%2,%3},{%4,%5,%6,%7},{%8,%9},{%0,%1,%2,%3};" \
        : "+f"((d)[0]), "+f"((d)[1]), "+f"((d)[2]), "+f"((d)[3]) \
        : "r"((a)[0]), "r"((a)[1]), "r"((a)[2]), "r"((a)[3]), "r"(b0), "r"(b1))

// ---------------------------------------------------------------------------
// Kernel B: split weights into K-packed [c][h][1024] fp16 pairs
// ---------------------------------------------------------------------------
__global__ void convert_w(const float* __restrict__ WL, const float* __restrict__ WM,
                          const float* __restrict__ WR)
{
    int idx = blockIdx.x * 256 + threadIdx.x;
    if (idx >= 3 * HH * KTOT) return;
    int q  = idx & 1023;
    int ch = idx >> 10;                  // c*HH + h
    float v;
    if (q < 320)      v = WL[(size_t)ch * 320 + q];
    else if (q < 704) v = WM[(size_t)ch * 384 + (q - 320)];
    else              v = WR[(size_t)ch * 320 + (q - 704)];
    __half bh = __float2half_rn(v);
    __half bm = __float2half_rn(v - __half2float(bh));
    g_Bh[idx] = bh;
    g_Bm[idx] = bm;
}

// ---------------------------------------------------------------------------
// Kernel C: HMMA GEMM with fused A split (math identical to R5).
//   grid = (64 t-tiles, 9 g);  block = 256 thr = 8 warps, 16 rows per warp.
//   2 blocks/SM (launch_bounds).  B ldmatrix uses x4 over n-chunk pairs.
// ---------------------------------------------------------------------------
#define KCH   32
#define ASTR  40                          // halfs per smem row (A and B)
#define OFF_AM 5120                       // halfs: 128*40
#define OFF_BH 10240
#define STAGE_HALFS 26240
#define STAGE_BYTES (STAGE_HALFS * 2)     // 52480
#define GEMM_SMEM (2 * STAGE_BYTES)       // 104960  (x2 blocks = 209920 <= 228KB)

__global__ __launch_bounds__(256, 2)
void gemm_mma(const float* __restrict__ x,
              const float* __restrict__ bL, const float* __restrict__ bM,
              const float* __restrict__ bR)
{
    extern __shared__ __half sm[];
    const uint32_t smb = smem_u32(sm);
    const int tid = threadIdx.x, wid = tid >> 5, lane = tid & 31;
    const int t = blockIdx.x;
    const int g = blockIdx.y, p = g / 3, c = g - p * 3;

    int Kp, q0, w, off;
    const float* bias;
    if (p == 0)      { Kp = 320; q0 = 0;   w = 10; off = 0;  bias = bL; }
    else if (p == 1) { Kp = 384; q0 = 320; w = 12; off = 10; bias = bM; }
    else             { Kp = 320; q0 = 704; w = 10; off = 22; bias = bR; }
    bias += c * HH;
    const int nch = Kp / KCH;

    const float* xc = x + (size_t)t * 128 * 3072 + (size_t)c * 1024;
    const size_t bbase = (size_t)c * HH * KTOT + q0;
    const __half* Bsrc[2] = { g_Bh + bbase, g_Bm + bbase };

    float acc[25][4];
    #pragma unroll
    for (int n = 0; n < 25; n++)
        #pragma unroll
        for (int j = 0; j < 4; j++) acc[n][j] = 0.f;

    // --- A: gathered fp32 float2 loads (local packed index decomposition) ---
    float2 areg[8];
    auto loadA = [&](int koff) {
        #pragma unroll
        for (int s = 0; s < 8; s++) {
            int i = tid + s * 256;            // 2048 float2 per stage
            int row = i >> 4, j = i & 15;
            int ql = koff + j * 2;            // local packed k (even)
            int grp = ql / w, l = ql - grp * w;
            areg[s] = *(const float2*)(xc + (size_t)row * 3072 + grp * 32 + off + l);
        }
    };
    auto stsA = [&](int buf) {
        __half* base = sm + buf * STAGE_HALFS;
        #pragma unroll
        for (int s = 0; s < 8; s++) {
            int i = tid + s * 256;
            int row = i >> 4, j = i & 15;
            float vx = areg[s].x, vy = areg[s].y;
            __half hx = __float2half_rn(vx), hy = __float2half_rn(vy);
            __half mx = __float2half_rn(vx - __half2float(hx));
            __half my = __float2half_rn(vy - __half2float(hy));
            int pos = row * ASTR + j * 2;
            *(__half2*)(base + pos)          = __halves2half2(hx, hy);
            *(__half2*)(base + OFF_AM + pos) = __halves2half2(mx, my);
        }
    };
    auto loadB = [&](int buf, int koff) {
        const uint32_t sb = smb + buf * STAGE_BYTES;
        #pragma unroll
        for (int s2 = 0; s2 < 2; s2++) {
            for (int i = tid; i < 800; i += 256) {
                int row = i >> 2, seg = i & 3;
                uint32_t dst = sb + (OFF_BH + s2 * 8000 + row * ASTR + seg * 8) * 2;
                CP16(dst, Bsrc[s2] + (size_t)row * KTOT + koff + seg * 8);
            }
        }
    };

    // prologue: stage 0
    loadA(0);
    loadB(0, 0);
    CP_COMMIT();
    stsA(0);

    // B ldmatrix lane mapping (x4 over n-chunk pairs):
    //   matrices 0,1 = rows r..r+7 (k0,k8); matrices 2,3 = rows r+8..r+15.
    const int brow = lane & 7;
    const int bk   = ((lane >> 3) & 1) * 8;   // k-half (halfs)
    const int bnhi = (lane >> 4) * 8;         // +8 rows for matrices 2,3

    for (int ch = 0; ch < nch; ch++) {
        if (ch + 1 < nch) {
            loadA((ch + 1) * KCH);
            loadB((ch + 1) & 1, (ch + 1) * KCH);
        }
        CP_COMMIT();
        CP_WAIT1();                           // B(ch) landed
        __syncthreads();                      // A(ch) STS visible

        const uint32_t sb = smb + (ch & 1) * STAGE_BYTES;
        #pragma unroll
        for (int kk = 0; kk < 2; kk++) {
            uint32_t ah[4], am[4];
            uint32_t aaddr = sb + ((wid * 16 + (lane & 15)) * ASTR + kk * 16 + (lane >> 4) * 8) * 2;
            LDSM_X4(ah, aaddr);
            LDSM_X4(am, aaddr + OFF_AM * 2);

            // 12 n-chunk pairs via x4
            #pragma unroll
            for (int i = 0; i < 12; i++) {
                uint32_t bh4[4], bm4[4];
                uint32_t ba = sb + (OFF_BH + (i * 16 + bnhi + brow) * ASTR + kk * 16 + bk) * 2;
                LDSM_X4(bh4, ba);
                LDSM_X4(bm4, ba + 8000 * 2);
                MMA16816(acc[2 * i],     ah, bh4[0], bh4[1]);
                MMA16816(acc[2 * i],     ah, bm4[0], bm4[1]);
                MMA16816(acc[2 * i],     am, bh4[0], bh4[1]);
                MMA16816(acc[2 * i + 1], ah, bh4[2], bh4[3]);
                MMA16816(acc[2 * i + 1], ah, bm4[2], bm4[3]);
                MMA16816(acc[2 * i + 1], am, bh4[2], bh4[3]);
            }
            // last n-chunk (24): rows 192..199 via x2
            {
                uint32_t bh2[2], bm2[2];
                uint32_t ba = sb + (OFF_BH + (192 + brow) * ASTR + kk * 16 + bk) * 2;
                LDSM_X2(bh2, ba);
                LDSM_X2(bm2, ba + 8000 * 2);
                MMA16816(acc[24], ah, bh2[0], bh2[1]);
                MMA16816(acc[24], ah, bm2[0], bm2[1]);
                MMA16816(acc[24], am, bh2[0], bh2[1]);
            }
        }
        if (ch + 1 < nch) stsA((ch + 1) & 1);
        __syncthreads();
    }

    // Epilogue: direct stores with bias (rows = b; tile index == t)
    const int r0 = wid * 16 + (lane >> 2);
    float* dst = g_cur + ((size_t)t * 9 + g) * BB * HH;
    #pragma unroll
    for (int n = 0; n < 25; n++) {
        const int col = n * 8 + (lane & 3) * 2;
        const float b0 = bias[col], b1 = bias[col + 1];
        float2 v0 = { acc[n][0] + b0, acc[n][1] + b1 };
        float2 v1 = { acc[n][2] + b0, acc[n][3] + b1 };
        *(float2*)&dst[(size_t)r0 * HH + col]       = v0;
        *(float2*)&dst[(size_t)(r0 + 8) * HH + col] = v1;
    }
}

// ---------------------------------------------------------------------------
// Kernel D: fused hidden LIF scan + output GEMM + LI readout.
// ---------------------------------------------------------------------------
__global__ __launch_bounds__(480)
void fused_scan_out(const float* __restrict__ Wout,
                    const float* __restrict__ bout,
                    float* __restrict__ out)
{
    __shared__ float wo[2000];       // Wout[k][o][j]
    __shared__ float bo_s[40];
    __shared__ float part[1800];     // z partials [br][200]
    __shared__ float zs[200];        // z_sum over branches
    __shared__ float curo[40];       // cur_o[k*10+o] for current t

    const int b   = blockIdx.x;
    const int tid = threadIdx.x;
    const bool scan_thr = tid < 450;
    const int h4 = scan_thr ? (tid % 50) : 0;
    const int br = scan_thr ? (tid / 50) : 0;

    for (int i = tid; i < 2000; i += 480) wo[i] = Wout[i];
    if (tid < 40) bo_s[tid] = bout[tid];

    float4 v  = {0.f, 0.f, 0.f, 0.f};
    float4 cc = {0.f, 0.f, 0.f, 0.f};
    float vo[4] = {0.f, 0.f, 0.f, 0.f};
    float io[4] = {0.f, 0.f, 0.f, 0.f};

    const float4* cur4 = (const float4*)g_cur;
    float4 cb[2];
    if (scan_thr) cb[0] = cur4[((size_t)br * BB + b) * 50 + h4];
    __syncthreads();

    for (int t = 0; t < TT; t++) {
        const float4 cin = cb[t & 1];
        if (scan_thr && t + 1 < TT)
            cb[(t + 1) & 1] = cur4[((size_t)((t + 1) * 9 + br) * BB + b) * 50 + h4];

        if (scan_thr) {
            float4 z;
            float vdx = v.x + 0.1f * (cc.x - v.x);
            float vdy = v.y + 0.1f * (cc.y - v.y);
            float vdz = v.z + 0.1f * (cc.z - v.z);
            float vdw = v.w + 0.1f * (cc.w - v.w);
            z.x = (vdx > 1.0f) ? 1.0f : 0.0f;  v.x = (vdx > 1.0f) ? 0.0f : vdx;
            z.y = (vdy > 1.0f) ? 1.0f : 0.0f;  v.y = (vdy > 1.0f) ? 0.0f : vdy;
            z.z = (vdz > 1.0f) ? 1.0f : 0.0f;  v.z = (vdz > 1.0f) ? 0.0f : vdz;
            z.w = (vdw > 1.0f) ? 1.0f : 0.0f;  v.w = (vdw > 1.0f) ? 0.0f : vdw;
            cc.x = 0.8f * cc.x + cin.x;
            cc.y = 0.8f * cc.y + cin.y;
            cc.z = 0.8f * cc.z + cin.z;
            cc.w = 0.8f * cc.w + cin.w;
            ((float4*)part)[br * 50 + h4] = z;
        }
        __syncthreads();

        if (tid < 50) {                       // reduce 9 branches
            float4 s = ((float4*)part)[tid];
            #pragma unroll
            for (int r = 1; r < 9; r++) {
                float4 q = ((float4*)part)[r * 50 + tid];
                s.x += q.x; s.y += q.y; s.z += q.z; s.w += q.w;
            }
            ((float4*)zs)[tid] = s;
        }
        __syncthreads();

        if (tid < 40) {                       // output GEMM (float2 LDS)
            const int k = tid / 10;
            const float2* zp = (const float2*)&zs[k * 50];
            const float2* wp = (const float2*)&wo[tid * 50];
            float s = bo_s[tid];
            #pragma unroll
            for (int j = 0; j < 25; j++) {
                float2 a = zp[j], ww = wp[j];
                s = fmaf(a.x, ww.x, s);
                s = fmaf(a.y, ww.y, s);
            }
            curo[tid] = s;
        }
        __syncthreads();

        if (tid < 10) {                       // LI readout
            float s = 0.f;
            #pragma unroll
            for (int k = 0; k < 4; k++) {
                vo[k] = vo[k] + 0.1f * (io[k] - vo[k]);
                io[k] = 0.8f * io[k] + curo[k * 10 + tid];
                s += vo[k];
            }
            out[((size_t)t * BB + b) * 10 + tid] = s;
        }
    }
}

// ---------------------------------------------------------------------------
extern "C" void kernel_launch(void* const* d_in, const int* in_sizes, int n_in,
                              void* d_out, int out_size)
{
    const float* x    = (const float*)d_in[0];
    const float* WL   = (const float*)d_in[1];
    const float* bL   = (const float*)d_in[2];
    const float* WM   = (const float*)d_in[3];
    const float* bM   = (const float*)d_in[4];
    const float* WR   = (const float*)d_in[5];
    const float* bR   = (const float*)d_in[6];
    const float* Wout = (const float*)d_in[7];
    const float* bout = (const float*)d_in[8];
    float* out = (float*)d_out;

    cudaFuncSetAttribute(gemm_mma, cudaFuncAttributeMaxDynamicSharedMemorySize, GEMM_SMEM);

    convert_w<<<(3 * HH * KTOT + 255) / 256, 256>>>(WL, WM, WR);
    gemm_mma<<<dim3(64, 9), 256, GEMM_SMEM>>>(x, bL, bM, bR);
    fused_scan_out<<<128, 480>>>(Wout, bout, out);
}

// round 7
// speedup vs baseline: 1.0614x; 1.0614x over previous
#include <cuda_runtime.h>
#include <cuda_fp16.h>
#include <cstdint>

#define TT 64
#define BB 128
#define HH 200
#define RROWS 8192      // T*B
#define KTOT 1024       // packed K per channel (320 L + 384 M + 320 R)

// ---------------------------------------------------------------------------
// Scratch (__device__ globals; no cudaMalloc allowed)
// ---------------------------------------------------------------------------
__device__ float g_cur[(size_t)TT * 9 * BB * HH];    // [t][g][b][h]
__device__ __half g_Bh[(size_t)3 * HH * KTOT];       // hi fp16 split of W (K-packed)
__device__ __half g_Bm[(size_t)3 * HH * KTOT];       // lo fp16 split

// ---------------------------------------------------------------------------
// PTX helpers (plain sm_103-compatible: mma.sync / ldmatrix / cp.async)
// ---------------------------------------------------------------------------
__device__ __forceinline__ uint32_t smem_u32(const void* p) {
    uint32_t a;
    asm("{ .reg .u64 t; cvta.to.shared.u64 t, %1; cvt.u32.u64 %0, t; }" : "=r"(a) : "l"(p));
    return a;
}

#define CP16(dst, src) \
    asm volatile("cp.async.cg.shared.global [%0], [%1], 16;" :: "r"(dst), "l"(src) : "memory")
#define CP_COMMIT() asm volatile("cp.async.commit_group;" ::: "memory")
#define CP_WAIT1()  asm volatile("cp.async.wait_group 1;" ::: "memory")

#define LDSM_X4(r, addr) \
    asm volatile("ldmatrix.sync.aligned.m8n8.x4.shared.b16 {%0,%1,%2,%3}, [%4];" \
        : "=r"((r)[0]), "=r"((r)[1]), "=r"((r)[2]), "=r"((r)[3]) : "r"(addr))
#define LDSM_X2(r, addr) \
    asm volatile("ldmatrix.sync.aligned.m8n8.x2.shared.b16 {%0,%1}, [%2];" \
        : "=r"((r)[0]), "=r"((r)[1]) : "r"(addr))

#define MMA16816(d, a, b) \
    asm volatile("mma.sync.aligned.m16n8k16.row.col.f32.f16.f16.f32 " \
        "{%0,%1,%2,%3},{%4,%5,%6,%7},{%8,%9},{%0,%1,%2,%3};" \
        : "+f"((d)[0]), "+f"((d)[1]), "+f"((d)[2]), "+f"((d)[3]) \
        : "r"((a)[0]), "r"((a)[1]), "r"((a)[2]), "r"((a)[3]), "r"((b)[0]), "r"((b)[1]))

// ---------------------------------------------------------------------------
// Kernel B: split weights into K-packed [c][h][1024] fp16 pairs
// ---------------------------------------------------------------------------
__global__ void convert_w(const float* __restrict__ WL, const float* __restrict__ WM,
                          const float* __restrict__ WR)
{
    int idx = blockIdx.x * 256 + threadIdx.x;
    if (idx >= 3 * HH * KTOT) return;
    int q  = idx & 1023;
    int ch = idx >> 10;                  // c*HH + h
    float v;
    if (q < 320)      v = WL[(size_t)ch * 320 + q];
    else if (q < 704) v = WM[(size_t)ch * 384 + (q - 320)];
    else              v = WR[(size_t)ch * 320 + (q - 704)];
    __half bh = __float2half_rn(v);
    __half bm = __float2half_rn(v - __half2float(bh));
    g_Bh[idx] = bh;
    g_Bm[idx] = bm;
}

// ---------------------------------------------------------------------------
// Kernel C: HMMA GEMM with fused A split (math identical to R5).
//   grid = (64 t-tiles, 9 g);  block = 512 thr = 16 warps.
//   Warp (wA = wid&7) owns M strip wA*16..+16; (nh = wid>>3) owns N half:
//     nh=0 -> n-chunks [0,13), nh=1 -> [13,25).  acc = 13x4 = 52 regs.
//   K chunk = 32, double-buffered.  Smem rows padded to 40 halfs.
// ---------------------------------------------------------------------------
#define KCH   32
#define ASTR  40                          // halfs per smem row (A and B)
#define OFF_AM 5120                       // halfs: 128*40
#define OFF_BH 10240
#define STAGE_HALFS 26240
#define STAGE_BYTES (STAGE_HALFS * 2)     // 52480
#define GEMM_SMEM (2 * STAGE_BYTES)       // 104960

__global__ __launch_bounds__(512)
void gemm_mma(const float* __restrict__ x,
              const float* __restrict__ bL, const float* __restrict__ bM,
              const float* __restrict__ bR)
{
    extern __shared__ __half sm[];
    const uint32_t smb = smem_u32(sm);
    const int tid = threadIdx.x, wid = tid >> 5, lane = tid & 31;
    const int wA = wid & 7;               // M strip
    const int nh = wid >> 3;              // N half: 0 -> 13 chunks, 1 -> 12
    const int n0 = nh ? 13 : 0;
    const int nn = nh ? 12 : 13;
    const int t = blockIdx.x;
    const int g = blockIdx.y, p = g / 3, c = g - p * 3;

    int Kp, q0, w, off;
    const float* bias;
    if (p == 0)      { Kp = 320; q0 = 0;   w = 10; off = 0;  bias = bL; }
    else if (p == 1) { Kp = 384; q0 = 320; w = 12; off = 10; bias = bM; }
    else             { Kp = 320; q0 = 704; w = 10; off = 22; bias = bR; }
    bias += c * HH;
    const int nch = Kp / KCH;

    const float* xc = x + (size_t)t * 128 * 3072 + (size_t)c * 1024;
    const size_t bbase = (size_t)c * HH * KTOT + q0;
    const __half* Bsrc[2] = { g_Bh + bbase, g_Bm + bbase };

    float acc[13][4];
    #pragma unroll
    for (int n = 0; n < 13; n++)
        #pragma unroll
        for (int j = 0; j < 4; j++) acc[n][j] = 0.f;

    // --- A: gathered fp32 float2 loads (local packed index decomposition) ---
    float2 areg[4];                        // 2048 float2 / 512 thr
    auto loadA = [&](int koff) {
        #pragma unroll
        for (int s = 0; s < 4; s++) {
            int i = tid + s * 512;
            int row = i >> 4, j = i & 15;
            int ql = koff + j * 2;            // local packed k (even)
            int grp = ql / w, l = ql - grp * w;
            areg[s] = *(const float2*)(xc + (size_t)row * 3072 + grp * 32 + off + l);
        }
    };
    auto stsA = [&](int buf) {
        __half* base = sm + buf * STAGE_HALFS;
        #pragma unroll
        for (int s = 0; s < 4; s++) {
            int i = tid + s * 512;
            int row = i >> 4, j = i & 15;
            float vx = areg[s].x, vy = areg[s].y;
            __half hx = __float2half_rn(vx), hy = __float2half_rn(vy);
            __half mx = __float2half_rn(vx - __half2float(hx));
            __half my = __float2half_rn(vy - __half2float(hy));
            int pos = row * ASTR + j * 2;
            *(__half2*)(base + pos)          = __halves2half2(hx, hy);
            *(__half2*)(base + OFF_AM + pos) = __halves2half2(mx, my);
        }
    };
    auto loadB = [&](int buf, int koff) {
        const uint32_t sb = smb + buf * STAGE_BYTES;
        #pragma unroll
        for (int s2 = 0; s2 < 2; s2++) {
            for (int i = tid; i < 800; i += 512) {
                int row = i >> 2, seg = i & 3;
                uint32_t dst = sb + (OFF_BH + s2 * 8000 + row * ASTR + seg * 8) * 2;
                CP16(dst, Bsrc[s2] + (size_t)row * KTOT + koff + seg * 8);
            }
        }
    };

    // prologue: stage 0
    loadA(0);
    loadB(0, 0);
    CP_COMMIT();
    stsA(0);

    for (int ch = 0; ch < nch; ch++) {
        if (ch + 1 < nch) {
            loadA((ch + 1) * KCH);           // LDGs overlap compute below
            loadB((ch + 1) & 1, (ch + 1) * KCH);
        }
        CP_COMMIT();
        CP_WAIT1();                           // B(ch) landed
        __syncthreads();                      // A(ch) STS visible

        const uint32_t sb = smb + (ch & 1) * STAGE_BYTES;
        #pragma unroll
        for (int kk = 0; kk < 2; kk++) {
            uint32_t ah[4], am[4];
            uint32_t aaddr = sb + ((wA * 16 + (lane & 15)) * ASTR + kk * 16 + (lane >> 4) * 8) * 2;
            LDSM_X4(ah, aaddr);
            LDSM_X4(am, aaddr + OFF_AM * 2);
            uint32_t baddr = sb + (OFF_BH + (n0 * 8 + (lane & 7)) * ASTR + kk * 16 + ((lane >> 3) & 1) * 8) * 2;
            #pragma unroll
            for (int n = 0; n < 13; n++) {
                if (n >= nn) break;
                uint32_t bh[2], bm[2];
                uint32_t ba = baddr + n * (8 * ASTR) * 2;
                LDSM_X2(bh, ba);
                LDSM_X2(bm, ba + 8000 * 2);
                MMA16816(acc[n], ah, bh);     // hh
                MMA16816(acc[n], ah, bm);     // h*m
                MMA16816(acc[n], am, bh);     // m*h
            }
        }
        if (ch + 1 < nch) stsA((ch + 1) & 1); // prior reads of that buf done pre-sync
        __syncthreads();                      // protect B buf (ch+1)&1 overwrite
    }

    // Epilogue: direct stores with bias (rows = b; tile index == t)
    const int r0 = wA * 16 + (lane >> 2);
    float* dst = g_cur + ((size_t)t * 9 + g) * BB * HH;
    #pragma unroll
    for (int n = 0; n < 13; n++) {
        if (n >= nn) break;
        const int col = (n0 + n) * 8 + (lane & 3) * 2;
        const float b0 = bias[col], b1 = bias[col + 1];
        float2 v0 = { acc[n][0] + b0, acc[n][1] + b1 };
        float2 v1 = { acc[n][2] + b0, acc[n][3] + b1 };
        *(float2*)&dst[(size_t)r0 * HH + col]       = v0;
        *(float2*)&dst[(size_t)(r0 + 8) * HH + col] = v1;
    }
}

// ---------------------------------------------------------------------------
// Kernel D: fused hidden LIF scan + output GEMM + LI readout.
// ---------------------------------------------------------------------------
__global__ __launch_bounds__(480)
void fused_scan_out(const float* __restrict__ Wout,
                    const float* __restrict__ bout,
                    float* __restrict__ out)
{
    __shared__ float wo[2000];       // Wout[k][o][j]
    __shared__ float bo_s[40];
    __shared__ float part[1800];     // z partials [br][200]
    __shared__ float zs[200];        // z_sum over branches
    __shared__ float curo[40];       // cur_o[k*10+o] for current t

    const int b   = blockIdx.x;
    const int tid = threadIdx.x;
    const bool scan_thr = tid < 450;
    const int h4 = scan_thr ? (tid % 50) : 0;
    const int br = scan_thr ? (tid / 50) : 0;

    for (int i = tid; i < 2000; i += 480) wo[i] = Wout[i];
    if (tid < 40) bo_s[tid] = bout[tid];

    float4 v  = {0.f, 0.f, 0.f, 0.f};
    float4 cc = {0.f, 0.f, 0.f, 0.f};
    float vo[4] = {0.f, 0.f, 0.f, 0.f};
    float io[4] = {0.f, 0.f, 0.f, 0.f};

    const float4* cur4 = (const float4*)g_cur;
    float4 cb[2];
    if (scan_thr) cb[0] = cur4[((size_t)br * BB + b) * 50 + h4];
    __syncthreads();

    for (int t = 0; t < TT; t++) {
        const float4 cin = cb[t & 1];
        if (scan_thr && t + 1 < TT)
            cb[(t + 1) & 1] = cur4[((size_t)((t + 1) * 9 + br) * BB + b) * 50 + h4];

        if (scan_thr) {
            float4 z;
            float vdx = v.x + 0.1f * (cc.x - v.x);
            float vdy = v.y + 0.1f * (cc.y - v.y);
            float vdz = v.z + 0.1f * (cc.z - v.z);
            float vdw = v.w + 0.1f * (cc.w - v.w);
            z.x = (vdx > 1.0f) ? 1.0f : 0.0f;  v.x = (vdx > 1.0f) ? 0.0f : vdx;
            z.y = (vdy > 1.0f) ? 1.0f : 0.0f;  v.y = (vdy > 1.0f) ? 0.0f : vdy;
            z.z = (vdz > 1.0f) ? 1.0f : 0.0f;  v.z = (vdz > 1.0f) ? 0.0f : vdz;
            z.w = (vdw > 1.0f) ? 1.0f : 0.0f;  v.w = (vdw > 1.0f) ? 0.0f : vdw;
            cc.x = 0.8f * cc.x + cin.x;
            cc.y = 0.8f * cc.y + cin.y;
            cc.z = 0.8f * cc.z + cin.z;
            cc.w = 0.8f * cc.w + cin.w;
            ((float4*)part)[br * 50 + h4] = z;
        }
        __syncthreads();

        if (tid < 50) {                       // reduce 9 branches
            float4 s = ((float4*)part)[tid];
            #pragma unroll
            for (int r = 1; r < 9; r++) {
                float4 q = ((float4*)part)[r * 50 + tid];
                s.x += q.x; s.y += q.y; s.z += q.z; s.w += q.w;
            }
            ((float4*)zs)[tid] = s;
        }
        __syncthreads();

        if (tid < 40) {                       // output GEMM (float2 LDS)
            const int k = tid / 10;
            const float2* zp = (const float2*)&zs[k * 50];
            const float2* wp = (const float2*)&wo[tid * 50];
            float s = bo_s[tid];
            #pragma unroll
            for (int j = 0; j < 25; j++) {
                float2 a = zp[j], ww = wp[j];
                s = fmaf(a.x, ww.x, s);
                s = fmaf(a.y, ww.y, s);
            }
            curo[tid] = s;
        }
        __syncthreads();

        if (tid < 10) {                       // LI readout
            float s = 0.f;
            #pragma unroll
            for (int k = 0; k < 4; k++) {
                vo[k] = vo[k] + 0.1f * (io[k] - vo[k]);
                io[k] = 0.8f * io[k] + curo[k * 10 + tid];
                s += vo[k];
            }
            out[((size_t)t * BB + b) * 10 + tid] = s;
        }
    }
}

// ---------------------------------------------------------------------------
extern "C" void kernel_launch(void* const* d_in, const int* in_sizes, int n_in,
                              void* d_out, int out_size)
{
    const float* x    = (const float*)d_in[0];
    const float* WL   = (const float*)d_in[1];
    const float* bL   = (const float*)d_in[2];
    const float* WM   = (const float*)d_in[3];
    const float* bM   = (const float*)d_in[4];
    const float* WR   = (const float*)d_in[5];
    const float* bR   = (const float*)d_in[6];
    const float* Wout = (const float*)d_in[7];
    const float* bout = (const float*)d_in[8];
    float* out = (float*)d_out;

    cudaFuncSetAttribute(gemm_mma, cudaFuncAttributeMaxDynamicSharedMemorySize, GEMM_SMEM);

    convert_w<<<(3 * HH * KTOT + 255) / 256, 256>>>(WL, WM, WR);
    gemm_mma<<<dim3(64, 9), 512, GEMM_SMEM>>>(x, bL, bM, bR);
    fused_scan_out<<<128, 480>>>(Wout, bout, out);
}

// round 8
// speedup vs baseline: 1.3187x; 1.2424x over previous
#include <cuda_runtime.h>
#include <cuda_fp16.h>
#include <cstdint>

#define TT 64
#define BB 128
#define HH 200
#define RROWS 8192      // T*B
#define KTOT 1024       // packed K per channel (320 L + 384 M + 320 R)

// ---------------------------------------------------------------------------
// Scratch (__device__ globals; no cudaMalloc allowed)
// ---------------------------------------------------------------------------
__device__ float g_cur[(size_t)TT * 9 * BB * HH];    // [t][g][b][h]
__device__ __half g_Bh[(size_t)3 * HH * KTOT];       // hi fp16 split of W (K-packed)
__device__ __half g_Bm[(size_t)3 * HH * KTOT];       // lo fp16 split

// ---------------------------------------------------------------------------
// PTX helpers (plain sm_103-compatible: mma.sync / ldmatrix / cp.async)
// ---------------------------------------------------------------------------
__device__ __forceinline__ uint32_t smem_u32(const void* p) {
    uint32_t a;
    asm("{ .reg .u64 t; cvta.to.shared.u64 t, %1; cvt.u32.u64 %0, t; }" : "=r"(a) : "l"(p));
    return a;
}

#define CP16(dst, src) \
    asm volatile("cp.async.cg.shared.global [%0], [%1], 16;" :: "r"(dst), "l"(src) : "memory")
#define CP_COMMIT() asm volatile("cp.async.commit_group;" ::: "memory")
#define CP_WAIT1()  asm volatile("cp.async.wait_group 1;" ::: "memory")

#define LDSM_X4(r, addr) \
    asm volatile("ldmatrix.sync.aligned.m8n8.x4.shared.b16 {%0,%1,%2,%3}, [%4];" \
        : "=r"((r)[0]), "=r"((r)[1]), "=r"((r)[2]), "=r"((r)[3]) : "r"(addr))
#define LDSM_X2(r, addr) \
    asm volatile("ldmatrix.sync.aligned.m8n8.x2.shared.b16 {%0,%1}, [%2];" \
        : "=r"((r)[0]), "=r"((r)[1]) : "r"(addr))

#define MMA16816(d, a, b) \
    asm volatile("mma.sync.aligned.m16n8k16.row.col.f32.f16.f16.f32 " \
        "{%0,%1,%2,%3},{%4,%5,%6,%7},{%8,%9},{%0,%1,%2,%3};" \
        : "+f"((d)[0]), "+f"((d)[1]), "+f"((d)[2]), "+f"((d)[3]) \
        : "r"((a)[0]), "r"((a)[1]), "r"((a)[2]), "r"((a)[3]), "r"((b)[0]), "r"((b)[1]))

// ---------------------------------------------------------------------------
// Kernel B: split weights into K-packed [c][h][1024] fp16 pairs
// ---------------------------------------------------------------------------
__global__ void convert_w(const float* __restrict__ WL, const float* __restrict__ WM,
                          const float* __restrict__ WR)
{
    int idx = blockIdx.x * 256 + threadIdx.x;
    if (idx >= 3 * HH * KTOT) return;
    int q  = idx & 1023;
    int ch = idx >> 10;                  // c*HH + h
    float v;
    if (q < 320)      v = WL[(size_t)ch * 320 + q];
    else if (q < 704) v = WM[(size_t)ch * 384 + (q - 320)];
    else              v = WR[(size_t)ch * 320 + (q - 704)];
    __half bh = __float2half_rn(v);
    __half bm = __float2half_rn(v - __half2float(bh));
    g_Bh[idx] = bh;
    g_Bm[idx] = bm;
}

// ---------------------------------------------------------------------------
// Kernel C: HMMA GEMM with fused A split — exact R5 configuration (best measured).
//   grid = (64 t-tiles, 9 g);  block = 256 thr = 8 warps, 16 rows per warp.
// ---------------------------------------------------------------------------
#define KCH   32
#define ASTR  40                          // halfs per smem row (A and B)
#define OFF_AM 5120                       // halfs: 128*40
#define OFF_BH 10240
#define STAGE_HALFS 26240
#define STAGE_BYTES (STAGE_HALFS * 2)     // 52480
#define GEMM_SMEM (2 * STAGE_BYTES)       // 104960

__global__ __launch_bounds__(256)
void gemm_mma(const float* __restrict__ x,
              const float* __restrict__ bL, const float* __restrict__ bM,
              const float* __restrict__ bR)
{
    extern __shared__ __half sm[];
    const uint32_t smb = smem_u32(sm);
    const int tid = threadIdx.x, wid = tid >> 5, lane = tid & 31;
    const int t = blockIdx.x;
    const int g = blockIdx.y, p = g / 3, c = g - p * 3;

    int Kp, q0, w, off;
    const float* bias;
    if (p == 0)      { Kp = 320; q0 = 0;   w = 10; off = 0;  bias = bL; }
    else if (p == 1) { Kp = 384; q0 = 320; w = 12; off = 10; bias = bM; }
    else             { Kp = 320; q0 = 704; w = 10; off = 22; bias = bR; }
    bias += c * HH;
    const int nch = Kp / KCH;

    const float* xc = x + (size_t)t * 128 * 3072 + (size_t)c * 1024;
    const size_t bbase = (size_t)c * HH * KTOT + q0;
    const __half* Bsrc[2] = { g_Bh + bbase, g_Bm + bbase };

    float acc[25][4];
    #pragma unroll
    for (int n = 0; n < 25; n++)
        #pragma unroll
        for (int j = 0; j < 4; j++) acc[n][j] = 0.f;

    float2 areg[8];
    auto loadA = [&](int koff) {
        #pragma unroll
        for (int s = 0; s < 8; s++) {
            int i = tid + s * 256;
            int row = i >> 4, j = i & 15;
            int ql = koff + j * 2;            // local packed k (even)
            int grp = ql / w, l = ql - grp * w;
            areg[s] = *(const float2*)(xc + (size_t)row * 3072 + grp * 32 + off + l);
        }
    };
    auto stsA = [&](int buf) {
        __half* base = sm + buf * STAGE_HALFS;
        #pragma unroll
        for (int s = 0; s < 8; s++) {
            int i = tid + s * 256;
            int row = i >> 4, j = i & 15;
            float vx = areg[s].x, vy = areg[s].y;
            __half hx = __float2half_rn(vx), hy = __float2half_rn(vy);
            __half mx = __float2half_rn(vx - __half2float(hx));
            __half my = __float2half_rn(vy - __half2float(hy));
            int pos = row * ASTR + j * 2;
            *(__half2*)(base + pos)          = __halves2half2(hx, hy);
            *(__half2*)(base + OFF_AM + pos) = __halves2half2(mx, my);
        }
    };
    auto loadB = [&](int buf, int koff) {
        const uint32_t sb = smb + buf * STAGE_BYTES;
        #pragma unroll
        for (int s2 = 0; s2 < 2; s2++) {
            for (int i = tid; i < 800; i += 256) {
                int row = i >> 2, seg = i & 3;
                uint32_t dst = sb + (OFF_BH + s2 * 8000 + row * ASTR + seg * 8) * 2;
                CP16(dst, Bsrc[s2] + (size_t)row * KTOT + koff + seg * 8);
            }
        }
    };

    loadA(0);
    loadB(0, 0);
    CP_COMMIT();
    stsA(0);

    for (int ch = 0; ch < nch; ch++) {
        if (ch + 1 < nch) {
            loadA((ch + 1) * KCH);
            loadB((ch + 1) & 1, (ch + 1) * KCH);
        }
        CP_COMMIT();
        CP_WAIT1();
        __syncthreads();

        const uint32_t sb = smb + (ch & 1) * STAGE_BYTES;
        #pragma unroll
        for (int kk = 0; kk < 2; kk++) {
            uint32_t ah[4], am[4];
            uint32_t aaddr = sb + ((wid * 16 + (lane & 15)) * ASTR + kk * 16 + (lane >> 4) * 8) * 2;
            LDSM_X4(ah, aaddr);
            LDSM_X4(am, aaddr + OFF_AM * 2);
            uint32_t baddr = sb + (OFF_BH + (lane & 7) * ASTR + kk * 16 + ((lane >> 3) & 1) * 8) * 2;
            #pragma unroll
            for (int n = 0; n < 25; n++) {
                uint32_t bh[2], bm[2];
                uint32_t ba = baddr + n * (8 * ASTR) * 2;
                LDSM_X2(bh, ba);
                LDSM_X2(bm, ba + 8000 * 2);
                MMA16816(acc[n], ah, bh);     // hh
                MMA16816(acc[n], ah, bm);     // h*m
                MMA16816(acc[n], am, bh);     // m*h
            }
        }
        if (ch + 1 < nch) stsA((ch + 1) & 1);
        __syncthreads();
    }

    const int r0 = wid * 16 + (lane >> 2);
    float* dst = g_cur + ((size_t)t * 9 + g) * BB * HH;
    #pragma unroll
    for (int n = 0; n < 25; n++) {
        const int col = n * 8 + (lane & 3) * 2;
        const float b0 = bias[col], b1 = bias[col + 1];
        float2 v0 = { acc[n][0] + b0, acc[n][1] + b1 };
        float2 v1 = { acc[n][2] + b0, acc[n][3] + b1 };
        *(float2*)&dst[(size_t)r0 * HH + col]       = v0;
        *(float2*)&dst[(size_t)(r0 + 8) * HH + col] = v1;
    }
}

// ---------------------------------------------------------------------------
// Kernel D: fused scan, 4x-unrolled timesteps.
//   Per round (4 t's): prefetch next round (MLP=4, double-buffered), 4 LIF
//   steps in regs, 1 sync, 200-thr branch reduce (4 t's), 1 sync, 160-thr
//   output GEMM (4x40), 1 sync, LI readout does 4 sequential steps.
// ---------------------------------------------------------------------------
__global__ __launch_bounds__(480)
void fused_scan_out(const float* __restrict__ Wout,
                    const float* __restrict__ bout,
                    float* __restrict__ out)
{
    __shared__ float wo[2000];        // Wout[k][o][j]
    __shared__ float bo_s[40];
    __shared__ float part[4][1800];   // z partials [j][br][200]
    __shared__ float zs[4][200];      // z_sum [j][h]
    __shared__ float curo[4][40];     // cur_o [j][k*10+o]

    const int b   = blockIdx.x;
    const int tid = threadIdx.x;
    const bool scan_thr = tid < 450;
    const int h4 = scan_thr ? (tid % 50) : 0;
    const int br = scan_thr ? (tid / 50) : 0;

    for (int i = tid; i < 2000; i += 480) wo[i] = Wout[i];
    if (tid < 40) bo_s[tid] = bout[tid];

    float4 v  = {0.f, 0.f, 0.f, 0.f};
    float4 cc = {0.f, 0.f, 0.f, 0.f};
    float vo[4] = {0.f, 0.f, 0.f, 0.f};
    float io[4] = {0.f, 0.f, 0.f, 0.f};

    const float4* cur4 = (const float4*)g_cur;
    const size_t bh4 = (size_t)b * 50 + h4;   // + (t*9+br)*128*50

    float4 cin[2][4];
    if (scan_thr) {
        #pragma unroll
        for (int j = 0; j < 4; j++)
            cin[0][j] = cur4[(size_t)(j * 9 + br) * (BB * 50) + bh4];
    }
    __syncthreads();                          // wo/bo ready

    for (int r = 0; r < 16; r++) {
        const int buf = r & 1;
        if (scan_thr && r + 1 < 16) {
            #pragma unroll
            for (int j = 0; j < 4; j++)
                cin[buf ^ 1][j] = cur4[(size_t)((4 * (r + 1) + j) * 9 + br) * (BB * 50) + bh4];
        }

        if (scan_thr) {
            #pragma unroll
            for (int j = 0; j < 4; j++) {
                const float4 ci = cin[buf][j];
                float4 z;
                float vdx = v.x + 0.1f * (cc.x - v.x);
                float vdy = v.y + 0.1f * (cc.y - v.y);
                float vdz = v.z + 0.1f * (cc.z - v.z);
                float vdw = v.w + 0.1f * (cc.w - v.w);
                z.x = (vdx > 1.0f) ? 1.0f : 0.0f;  v.x = (vdx > 1.0f) ? 0.0f : vdx;
                z.y = (vdy > 1.0f) ? 1.0f : 0.0f;  v.y = (vdy > 1.0f) ? 0.0f : vdy;
                z.z = (vdz > 1.0f) ? 1.0f : 0.0f;  v.z = (vdz > 1.0f) ? 0.0f : vdz;
                z.w = (vdw > 1.0f) ? 1.0f : 0.0f;  v.w = (vdw > 1.0f) ? 0.0f : vdw;
                cc.x = 0.8f * cc.x + ci.x;
                cc.y = 0.8f * cc.y + ci.y;
                cc.z = 0.8f * cc.z + ci.z;
                cc.w = 0.8f * cc.w + ci.w;
                ((float4*)part[j])[br * 50 + h4] = z;
            }
        }
        __syncthreads();

        if (tid < 200) {                      // reduce 9 branches, 4 t's
            const int j = tid / 50, hq = tid % 50;
            float4 s = ((float4*)part[j])[hq];
            #pragma unroll
            for (int r2 = 1; r2 < 9; r2++) {
                float4 q = ((float4*)part[j])[r2 * 50 + hq];
                s.x += q.x; s.y += q.y; s.z += q.z; s.w += q.w;
            }
            ((float4*)zs[j])[hq] = s;
        }
        __syncthreads();

        if (tid < 160) {                      // output GEMM: 4 t's x 40
            const int j = tid / 40, rem = tid % 40;
            const int k = rem / 10;
            const float2* zp = (const float2*)&zs[j][k * 50];
            const float2* wp = (const float2*)&wo[rem * 50];
            float s = bo_s[rem];
            #pragma unroll
            for (int q = 0; q < 25; q++) {
                float2 a = zp[q], ww = wp[q];
                s = fmaf(a.x, ww.x, s);
                s = fmaf(a.y, ww.y, s);
            }
            curo[j][rem] = s;
        }
        __syncthreads();

        if (tid < 10) {                       // LI readout, 4 sequential steps
            #pragma unroll
            for (int j = 0; j < 4; j++) {
                float s = 0.f;
                #pragma unroll
                for (int k = 0; k < 4; k++) {
                    vo[k] = vo[k] + 0.1f * (io[k] - vo[k]);
                    io[k] = 0.8f * io[k] + curo[j][k * 10 + tid];
                    s += vo[k];
                }
                out[((size_t)(4 * r + j) * BB + b) * 10 + tid] = s;
            }
        }
        // next round's part writes are fenced by its first barrier
    }
}

// ---------------------------------------------------------------------------
extern "C" void kernel_launch(void* const* d_in, const int* in_sizes, int n_in,
                              void* d_out, int out_size)
{
    const float* x    = (const float*)d_in[0];
    const float* WL   = (const float*)d_in[1];
    const float* bL   = (const float*)d_in[2];
    const float* WM   = (const float*)d_in[3];
    const float* bM   = (const float*)d_in[4];
    const float* WR   = (const float*)d_in[5];
    const float* bR   = (const float*)d_in[6];
    const float* Wout = (const float*)d_in[7];
    const float* bout = (const float*)d_in[8];
    float* out = (float*)d_out;

    cudaFuncSetAttribute(gemm_mma, cudaFuncAttributeMaxDynamicSharedMemorySize, GEMM_SMEM);

    convert_w<<<(3 * HH * KTOT + 255) / 256, 256>>>(WL, WM, WR);
    gemm_mma<<<dim3(64, 9), 256, GEMM_SMEM>>>(x, bL, bM, bR);
    fused_scan_out<<<128, 480>>>(Wout, bout, out);
}